// round 9
// baseline (speedup 1.0000x reference)
#include <cuda_runtime.h>
#include <cuda_fp16.h>
#include <math.h>

#define BATCH 2
#define SEQ   2048
#define NH    16
#define HD    64
#define HID   1024
#define F3    3072
#define BS    (BATCH*SEQ)
#define NBH   (BATCH*NH)        // 32

// 0.125 * log2(e)
#define C2EXP 0.1803368801111204f

// ---------------- scratch (device globals) ---------------------------------
__device__ uint4 g_qkv16[(size_t)BS * F3 / 8];           // fp16 qkv, 25.2 MB
__device__ uint4 g_x16[(size_t)BS * HID / 8];            // fp16 x
__device__ uint4 g_wq16[(size_t)HID * F3 / 8];           // fp16 w_qkv
__device__ uint4 g_wo16[(size_t)HID * HID / 8];          // fp16 w_o
__device__ uint4 g_vals16[(size_t)BS * HID / 8];         // fp16 v*colsum
__device__ float g_z[NBH * SEQ];
__device__ float g_colsum[NBH * SEQ];

__device__ __forceinline__ float ex2f(float x) {
    float r; asm("ex2.approx.f32 %0, %1;" : "=f"(r) : "f"(x)); return r;
}
__device__ __forceinline__ unsigned sptr(const void* p) {
    return (unsigned)__cvta_generic_to_shared(p);
}
__device__ __forceinline__ void mma_f16(float* c, const unsigned* a, unsigned b0, unsigned b1) {
    asm volatile(
        "mma.sync.aligned.m16n8k16.row.col.f32.f16.f16.f32 "
        "{%0,%1,%2,%3}, {%4,%5,%6,%7}, {%8,%9}, {%0,%1,%2,%3};"
        : "+f"(c[0]), "+f"(c[1]), "+f"(c[2]), "+f"(c[3])
        : "r"(a[0]), "r"(a[1]), "r"(a[2]), "r"(a[3]), "r"(b0), "r"(b1));
}
__device__ __forceinline__ void ldsm4(unsigned* r, unsigned addr) {
    asm volatile("ldmatrix.sync.aligned.m8n8.x4.shared.b16 {%0,%1,%2,%3}, [%4];"
                 : "=r"(r[0]), "=r"(r[1]), "=r"(r[2]), "=r"(r[3]) : "r"(addr));
}
__device__ __forceinline__ void ldsm4t(unsigned* r, unsigned addr) {
    asm volatile("ldmatrix.sync.aligned.m8n8.x4.trans.shared.b16 {%0,%1,%2,%3}, [%4];"
                 : "=r"(r[0]), "=r"(r[1]), "=r"(r[2]), "=r"(r[3]) : "r"(addr));
}
__device__ __forceinline__ void cp16(unsigned dst, const void* src) {
    asm volatile("cp.async.cg.shared.global [%0], [%1], 16;" :: "r"(dst), "l"(src));
}
__device__ __forceinline__ unsigned pack_f16(float a, float b) {
    __half2 h = __floats2half2_rn(a, b);
    return *(unsigned*)&h;
}

// ======================= fp16 GEMM, 128x128 tile, cp.async 2-stage ==========
// A [M][K] fp16 row-major (ldaG granules/row), B [K][N] fp16 row-major (ldbG),
// C row-major: fp16 if OUT_F16 else fp32.  K multiple of 64.
template <bool OUT_F16>
__global__ __launch_bounds__(256, 2) void gemm_f16(
    const uint4* __restrict__ A, const uint4* __restrict__ B, void* __restrict__ Cv,
    int K, int ldaG, int ldbG, int ldc)
{
    extern __shared__ uint4 smem[];
    uint4* sA = smem;           // [2][1024]  (128 rows x 8 granules)
    uint4* sB = smem + 2048;    // [2][1024]  (64 k-rows x 16 n-granules)

    const int tid = threadIdx.x, lane = tid & 31, wid = tid >> 5;
    const int wm = wid & 1, wn = wid >> 1, qr = lane >> 2, qc = lane & 3;
    const int grp = lane >> 3, lrow = lane & 7;
    const int bm0 = blockIdx.y * 128;
    const int bn0g = blockIdx.x * 16;          // n granule base
    const int NC = K / 64;

    const int a_row = tid & 127, a_gb = (tid >> 7) * 4;
    const int b_row = tid & 63,  b_gb = (tid >> 6) * 4;

    auto issue = [&](int c) {
        int s = c & 1;
        const uint4* ag = A + (long)(bm0 + a_row) * ldaG + c * 8 + a_gb;
        uint4* ad = sA + s * 1024 + a_row * 8;
#pragma unroll
        for (int i = 0; i < 4; i++)
            cp16(sptr(ad + ((a_gb + i) ^ (a_row & 7))), ag + i);
        const uint4* bg = B + (long)(c * 64 + b_row) * ldbG + bn0g + b_gb;
        uint4* bd = sB + s * 1024 + b_row * 16;
#pragma unroll
        for (int i = 0; i < 4; i++)
            cp16(sptr(bd + ((b_gb + i) ^ (b_row & 7))), bg + i);
        asm volatile("cp.async.commit_group;");
    };

    issue(0);
    if (NC > 1) issue(1);

    float acc[4][4][4];
#pragma unroll
    for (int i = 0; i < 4; i++)
#pragma unroll
        for (int j = 0; j < 4; j++)
#pragma unroll
            for (int f = 0; f < 4; f++) acc[i][j][f] = 0.f;

#pragma unroll 1
    for (int c = 0; c < NC; c++) {
        asm volatile("cp.async.wait_group 1;");
        __syncthreads();
        const uint4* sAs = sA + (c & 1) * 1024;
        const uint4* sBs = sB + (c & 1) * 1024;

#pragma unroll
        for (int ks = 0; ks < 4; ks++) {
            unsigned af[4][4], bfr[2][4];
#pragma unroll
            for (int i = 0; i < 4; i++) {
                int row = wm * 64 + i * 16 + lrow + (grp & 1) * 8;
                int g = (2 * ks + (grp >> 1)) ^ (row & 7);
                ldsm4(af[i], sptr(sAs + row * 8 + g));
            }
#pragma unroll
            for (int jp = 0; jp < 2; jp++) {
                int brow = ks * 16 + (grp & 1) * 8 + lrow;
                int bg = (wn * 4 + jp * 2 + (grp >> 1)) ^ (brow & 7);
                ldsm4t(bfr[jp], sptr(sBs + brow * 16 + bg));
            }
#pragma unroll
            for (int i = 0; i < 4; i++)
#pragma unroll
                for (int jp = 0; jp < 2; jp++) {
                    mma_f16(acc[i][jp * 2 + 0], af[i], bfr[jp][0], bfr[jp][1]);
                    mma_f16(acc[i][jp * 2 + 1], af[i], bfr[jp][2], bfr[jp][3]);
                }
        }
        __syncthreads();
        if (c + 2 < NC) issue(c + 2);
    }

#pragma unroll
    for (int i = 0; i < 4; i++) {
        long row = bm0 + wm * 64 + i * 16 + qr;
#pragma unroll
        for (int j = 0; j < 4; j++) {
            int col = bn0g * 8 + wn * 32 + j * 8 + 2 * qc;
            if (OUT_F16) {
                __half* C = (__half*)Cv;
                *(unsigned*)(C + row * ldc + col) = pack_f16(acc[i][j][0], acc[i][j][1]);
                *(unsigned*)(C + (row + 8) * ldc + col) = pack_f16(acc[i][j][2], acc[i][j][3]);
            } else {
                float* C = (float*)Cv;
                *(float2*)(C + row * ldc + col) = make_float2(acc[i][j][0], acc[i][j][1]);
                *(float2*)(C + (row + 8) * ldc + col) = make_float2(acc[i][j][2], acc[i][j][3]);
            }
        }
    }
}

// ======================= fp32 -> fp16 convert (granules of 8) ===============
__global__ __launch_bounds__(256) void cvtb_kernel(
    const float4* __restrict__ src, uint4* __restrict__ dst, long n)
{
    long i = (long)blockIdx.x * 256 + threadIdx.x;
    if (i >= n) return;
    float4 v0 = src[2 * i], v1 = src[2 * i + 1];
    dst[i] = make_uint4(pack_f16(v0.x, v0.y), pack_f16(v0.z, v0.w),
                        pack_f16(v1.x, v1.y), pack_f16(v1.z, v1.w));
}

// ======================= fp16 QK^T pass (ldmatrix + m16n8k16) ===============
// reads q,k granules directly from fp16 qkv (ld = 384 granules/row)
template <int MODE>
__global__ __launch_bounds__(256, 2) void qk_kernel(
    const uint4* __restrict__ qkv16, float* __restrict__ Z, float* __restrict__ colsum)
{
    __shared__ uint4 Qs[128 * 8];      // 16 KB
    __shared__ uint4 Ks[128 * 8];      // 16 KB
    __shared__ float s_red[512];

    const int tid = threadIdx.x, lane = tid & 31, wid = tid >> 5;
    const int wm = wid & 1, wn = wid >> 1, qr = lane >> 2, qc = lane & 3;
    const int bz = blockIdx.z;
    const int b = bz >> 4, h = bz & 15;
    const int bm0 = blockIdx.y * 128, bn0 = blockIdx.x * 128;

    const uint4* Qg = qkv16 + (long)b * SEQ * 384 + h * 8;
    const uint4* Kg = Qg + 128;        // k part starts at granule 128

    const int cg = tid & 7, rb = tid >> 3;
#pragma unroll
    for (int r = 0; r < 4; r++) {
        int row = rb + r * 32;
        uint4 vq = Qg[(long)(bm0 + row) * 384 + cg];
        uint4 vk = Kg[(long)(bn0 + row) * 384 + cg];
        int sw = row * 8 + (cg ^ (row & 7));
        Qs[sw] = vq;
        Ks[sw] = vk;
    }
    if (MODE == 2 && tid < 128)
        s_red[tid] = 1.0f / Z[(long)bz * SEQ + bm0 + tid];
    __syncthreads();

    float izreg[4][2];
    if (MODE == 2) {
#pragma unroll
        for (int i = 0; i < 4; i++)
#pragma unroll
            for (int h2 = 0; h2 < 2; h2++)
                izreg[i][h2] = s_red[wm * 64 + i * 16 + h2 * 8 + qr];
    }

    float acc[4][4][4];
#pragma unroll
    for (int i = 0; i < 4; i++)
#pragma unroll
        for (int j = 0; j < 4; j++)
#pragma unroll
            for (int f = 0; f < 4; f++) acc[i][j][f] = 0.f;

    const int grp = lane >> 3, lrow = lane & 7;
    const int a_roff = (grp & 1) * 8, a_kg = grp >> 1;
    const int b_roff = (grp >> 1) * 8, b_kg = grp & 1;

#pragma unroll
    for (int g = 0; g < 4; g++) {
        unsigned af[4][4], bfr[2][4];
#pragma unroll
        for (int i = 0; i < 4; i++) {
            int row = wm * 64 + i * 16 + lrow + a_roff;
            int gr = (2 * g + a_kg) ^ (row & 7);
            ldsm4(af[i], sptr(&Qs[row * 8 + gr]));
        }
#pragma unroll
        for (int jp = 0; jp < 2; jp++) {
            int row = wn * 32 + jp * 16 + lrow + b_roff;
            int gr = (2 * g + b_kg) ^ (row & 7);
            ldsm4(bfr[jp], sptr(&Ks[row * 8 + gr]));
        }
#pragma unroll
        for (int i = 0; i < 4; i++)
#pragma unroll
            for (int jp = 0; jp < 2; jp++) {
                mma_f16(acc[i][jp * 2 + 0], af[i], bfr[jp][0], bfr[jp][1]);
                mma_f16(acc[i][jp * 2 + 1], af[i], bfr[jp][2], bfr[jp][3]);
            }
    }

    if (MODE == 1) {
        float lz[4][2];
#pragma unroll
        for (int i = 0; i < 4; i++)
#pragma unroll
            for (int h2 = 0; h2 < 2; h2++) {
                float z = 0.f;
#pragma unroll
                for (int j = 0; j < 4; j++) {
                    z += ex2f(acc[i][j][2 * h2]     * C2EXP);
                    z += ex2f(acc[i][j][2 * h2 + 1] * C2EXP);
                }
                lz[i][h2] = z;
            }
#pragma unroll
        for (int d = 1; d <= 2; d <<= 1)
#pragma unroll
            for (int i = 0; i < 4; i++)
#pragma unroll
                for (int h2 = 0; h2 < 2; h2++)
                    lz[i][h2] += __shfl_xor_sync(0xffffffffu, lz[i][h2], d);
        __syncthreads();
        if (qc == 0)
#pragma unroll
            for (int i = 0; i < 4; i++)
#pragma unroll
                for (int h2 = 0; h2 < 2; h2++)
                    s_red[wn * 128 + wm * 64 + i * 16 + h2 * 8 + qr] = lz[i][h2];
        __syncthreads();
        if (tid < 128) {
            float z = s_red[tid] + s_red[128 + tid] + s_red[256 + tid] + s_red[384 + tid];
            atomicAdd(&Z[(long)bz * SEQ + bm0 + tid], z);
        }
    }

    if (MODE == 2) {
        float cs[4][2];
#pragma unroll
        for (int j = 0; j < 4; j++) { cs[j][0] = 0.f; cs[j][1] = 0.f; }
#pragma unroll
        for (int i = 0; i < 4; i++)
#pragma unroll
            for (int h2 = 0; h2 < 2; h2++) {
                float iz = izreg[i][h2];
#pragma unroll
                for (int j = 0; j < 4; j++) {
                    cs[j][0] += ex2f(acc[i][j][2 * h2]     * C2EXP) * iz;
                    cs[j][1] += ex2f(acc[i][j][2 * h2 + 1] * C2EXP) * iz;
                }
            }
#pragma unroll
        for (int d = 4; d <= 16; d <<= 1)
#pragma unroll
            for (int j = 0; j < 4; j++) {
                cs[j][0] += __shfl_xor_sync(0xffffffffu, cs[j][0], d);
                cs[j][1] += __shfl_xor_sync(0xffffffffu, cs[j][1], d);
            }
        if (qr == 0) {
#pragma unroll
            for (int j = 0; j < 4; j++) {
                int col = bn0 + wn * 32 + j * 8 + 2 * qc;
                atomicAdd(&colsum[(long)bz * SEQ + col],     cs[j][0]);
                atomicAdd(&colsum[(long)bz * SEQ + col + 1], cs[j][1]);
            }
        }
    }
}

// ======================= v * colsum -> fp16 vals ============================
__global__ __launch_bounds__(256) void scale_v16_kernel(
    const uint4* __restrict__ qkv16, const float* __restrict__ cs,
    uint4* __restrict__ vals16)
{
    long i = (long)blockIdx.x * 256 + threadIdx.x;   // BS*128 granules
    long bs = i >> 7;
    int fg = (int)(i & 127);
    int h = fg >> 3;
    int b = (int)(bs >> 11), s = (int)(bs & (SEQ - 1));
    float sc = cs[(((long)b << 4) + h) * SEQ + s];
    uint4 v = qkv16[bs * 384 + 256 + fg];
    uint4 o;
    unsigned* vp = (unsigned*)&v;
    unsigned* op = (unsigned*)&o;
#pragma unroll
    for (int j = 0; j < 4; j++) {
        float2 f = __half22float2(*(__half2*)&vp[j]);
        op[j] = pack_f16(f.x * sc, f.y * sc);
    }
    vals16[i] = o;
}

// ---------------- zero accumulators ----------------------------------------
__global__ void zero_kernel(float* __restrict__ z, float* __restrict__ cs)
{
    int i = blockIdx.x * 256 + threadIdx.x;
    if (i < NBH * SEQ) { z[i] = 0.f; cs[i] = 0.f; }
}

// ---------------- launcher --------------------------------------------------
#define GEMM_SMEM 65536

extern "C" void kernel_launch(void* const* d_in, const int* in_sizes, int n_in,
                              void* d_out, int out_size)
{
    const float* x     = (const float*)d_in[0];
    const float* w_qkv = (const float*)d_in[1];
    const float* w_o   = (const float*)d_in[2];
    float* out = (float*)d_out;

    float *p_z, *p_cs;
    uint4 *p_qkv16, *p_x16, *p_wq16, *p_wo16, *p_vals16;
    cudaGetSymbolAddress((void**)&p_z,      g_z);
    cudaGetSymbolAddress((void**)&p_cs,     g_colsum);
    cudaGetSymbolAddress((void**)&p_qkv16,  g_qkv16);
    cudaGetSymbolAddress((void**)&p_x16,    g_x16);
    cudaGetSymbolAddress((void**)&p_wq16,   g_wq16);
    cudaGetSymbolAddress((void**)&p_wo16,   g_wo16);
    cudaGetSymbolAddress((void**)&p_vals16, g_vals16);

    cudaFuncSetAttribute(gemm_f16<true>,  cudaFuncAttributeMaxDynamicSharedMemorySize, GEMM_SMEM);
    cudaFuncSetAttribute(gemm_f16<false>, cudaFuncAttributeMaxDynamicSharedMemorySize, GEMM_SMEM);

    dim3 blk(256);

    // 0. zero accumulators
    zero_kernel<<<(NBH * SEQ + 255) / 256, blk>>>(p_z, p_cs);

    // 0b. convert inputs to fp16
    cvtb_kernel<<<(int)(((long)BS * HID / 8 + 255) / 256), blk>>>(
        (const float4*)x, p_x16, (long)BS * HID / 8);
    cvtb_kernel<<<(int)(((long)HID * F3 / 8 + 255) / 256), blk>>>(
        (const float4*)w_qkv, p_wq16, (long)HID * F3 / 8);
    cvtb_kernel<<<(int)(((long)HID * HID / 8 + 255) / 256), blk>>>(
        (const float4*)w_o, p_wo16, (long)HID * HID / 8);

    // 1. qkv(fp16) = x16 @ wq16
    gemm_f16<true><<<dim3(F3 / 128, BS / 128), blk, GEMM_SMEM>>>(
        p_x16, p_wq16, p_qkv16, HID, HID / 8, F3 / 8, F3);

    // 2. pass 1: Z[q] = sum_k exp(q.k/8)
    qk_kernel<1><<<dim3(SEQ / 128, SEQ / 128, NBH), blk>>>(p_qkv16, p_z, nullptr);

    // 3. pass 2: colsum[k] = sum_q exp(q.k/8)/Z[q]
    qk_kernel<2><<<dim3(SEQ / 128, SEQ / 128, NBH), blk>>>(p_qkv16, p_z, p_cs);

    // 4. vals16 = fp16(v * colsum)
    scale_v16_kernel<<<(int)(((long)BS * HID / 8) / 256), blk>>>(p_qkv16, p_cs, p_vals16);

    // 5. out(fp32) = vals16 @ wo16
    gemm_f16<false><<<dim3(HID / 128, BS / 128), blk, GEMM_SMEM>>>(
        p_vals16, p_wo16, out, HID, HID / 8, HID / 8, HID);
}

// round 10
// speedup vs baseline: 1.3735x; 1.3735x over previous
#include <cuda_runtime.h>
#include <cuda_fp16.h>
#include <math.h>

#define BATCH 2
#define SEQ   2048
#define NH    16
#define HD    64
#define HID   1024
#define F3    3072
#define BS    (BATCH*SEQ)
#define NBH   (BATCH*NH)        // 32

// 0.125 * log2(e)
#define C2EXP 0.1803368801111204f

// ---------------- scratch (device globals) ---------------------------------
__device__ uint4 g_qkv16[(size_t)BS * F3 / 8];           // fp16 qkv, 25.2 MB
__device__ uint4 g_x16[(size_t)BS * HID / 8];            // fp16 x
__device__ uint4 g_wq16[(size_t)HID * F3 / 8];           // fp16 w_qkv
__device__ uint4 g_wo16[(size_t)HID * HID / 8];          // fp16 w_o
__device__ uint4 g_vals16[(size_t)BS * HID / 8];         // fp16 v*colsum
__device__ float g_z[NBH * SEQ];
__device__ float g_colsum[NBH * SEQ];

__device__ __forceinline__ float ex2f(float x) {
    float r; asm("ex2.approx.f32 %0, %1;" : "=f"(r) : "f"(x)); return r;
}
__device__ __forceinline__ unsigned sptr(const void* p) {
    return (unsigned)__cvta_generic_to_shared(p);
}
__device__ __forceinline__ void mma_f16(float* c, const unsigned* a, unsigned b0, unsigned b1) {
    asm volatile(
        "mma.sync.aligned.m16n8k16.row.col.f32.f16.f16.f32 "
        "{%0,%1,%2,%3}, {%4,%5,%6,%7}, {%8,%9}, {%0,%1,%2,%3};"
        : "+f"(c[0]), "+f"(c[1]), "+f"(c[2]), "+f"(c[3])
        : "r"(a[0]), "r"(a[1]), "r"(a[2]), "r"(a[3]), "r"(b0), "r"(b1));
}
__device__ __forceinline__ void ldsm4(unsigned* r, unsigned addr) {
    asm volatile("ldmatrix.sync.aligned.m8n8.x4.shared.b16 {%0,%1,%2,%3}, [%4];"
                 : "=r"(r[0]), "=r"(r[1]), "=r"(r[2]), "=r"(r[3]) : "r"(addr));
}
__device__ __forceinline__ void ldsm4t(unsigned* r, unsigned addr) {
    asm volatile("ldmatrix.sync.aligned.m8n8.x4.trans.shared.b16 {%0,%1,%2,%3}, [%4];"
                 : "=r"(r[0]), "=r"(r[1]), "=r"(r[2]), "=r"(r[3]) : "r"(addr));
}
__device__ __forceinline__ void cp16(unsigned dst, const void* src) {
    asm volatile("cp.async.cg.shared.global [%0], [%1], 16;" :: "r"(dst), "l"(src));
}
__device__ __forceinline__ unsigned pack_f16(float a, float b) {
    __half2 h = __floats2half2_rn(a, b);
    return *(unsigned*)&h;
}

// ======================= fp16 GEMM, 128x128 tile, cp.async 3-stage ==========
// A [M][K] fp16 row-major (ldaG granules/row), B [K][N] fp16 row-major (ldbG),
// C row-major: fp16 if OUT_F16 else fp32.  K multiple of 64.
// Loaders are row-coalesced: each cp.async instruction covers contiguous 128B+.
template <bool OUT_F16>
__global__ __launch_bounds__(256, 2) void gemm_f16(
    const uint4* __restrict__ A, const uint4* __restrict__ B, void* __restrict__ Cv,
    int K, int ldaG, int ldbG, int ldc)
{
    extern __shared__ uint4 smem[];
    uint4* sA = smem;           // [3][1024]  (128 rows x 8 granules)
    uint4* sB = smem + 3072;    // [3][1024]  (64 k-rows x 16 n-granules)

    const int tid = threadIdx.x, lane = tid & 31, wid = tid >> 5;
    const int wm = wid & 1, wn = wid >> 1, qr = lane >> 2, qc = lane & 3;
    const int grp = lane >> 3, lrow = lane & 7;
    const int bm0 = blockIdx.y * 128;
    const int bn0g = blockIdx.x * 16;          // n granule base
    const int NC = K / 64;

    // coalesced loader lanes: A: 8 granules/row, B: 16 granules/row
    const int cgA = tid & 7,  rowA0 = tid >> 3;    // rows 0..31 (+r*32)
    const int cgB = tid & 15, rowB0 = tid >> 4;    // rows 0..15 (+r*16)

    auto issue = [&](int c, int s) {
        const uint4* ag = A + (long)(bm0 + rowA0) * ldaG + c * 8 + cgA;
        uint4* ad = sA + s * 1024;
#pragma unroll
        for (int r = 0; r < 4; r++) {
            int row = rowA0 + r * 32;
            cp16(sptr(ad + row * 8 + (cgA ^ (row & 7))), ag + (long)r * 32 * ldaG);
        }
        const uint4* bg = B + (long)(c * 64 + rowB0) * ldbG + bn0g + cgB;
        uint4* bd = sB + s * 1024;
#pragma unroll
        for (int r = 0; r < 4; r++) {
            int row = rowB0 + r * 16;
            cp16(sptr(bd + row * 16 + (cgB ^ (row & 7))), bg + (long)r * 16 * ldbG);
        }
        asm volatile("cp.async.commit_group;");
    };

    issue(0, 0);
    if (NC > 1) issue(1, 1);
    if (NC > 2) issue(2, 2);

    float acc[4][4][4];
#pragma unroll
    for (int i = 0; i < 4; i++)
#pragma unroll
        for (int j = 0; j < 4; j++)
#pragma unroll
            for (int f = 0; f < 4; f++) acc[i][j][f] = 0.f;

    int s = 0;
#pragma unroll 1
    for (int c = 0; c < NC; c++) {
        asm volatile("cp.async.wait_group 2;");
        __syncthreads();
        const uint4* sAs = sA + s * 1024;
        const uint4* sBs = sB + s * 1024;

#pragma unroll
        for (int ks = 0; ks < 4; ks++) {
            unsigned af[4][4], bfr[2][4];
#pragma unroll
            for (int i = 0; i < 4; i++) {
                int row = wm * 64 + i * 16 + lrow + (grp & 1) * 8;
                int g = (2 * ks + (grp >> 1)) ^ (row & 7);
                ldsm4(af[i], sptr(sAs + row * 8 + g));
            }
#pragma unroll
            for (int jp = 0; jp < 2; jp++) {
                int brow = ks * 16 + (grp & 1) * 8 + lrow;
                int bg = (wn * 4 + jp * 2 + (grp >> 1)) ^ (brow & 7);
                ldsm4t(bfr[jp], sptr(sBs + brow * 16 + bg));
            }
#pragma unroll
            for (int i = 0; i < 4; i++)
#pragma unroll
                for (int jp = 0; jp < 2; jp++) {
                    mma_f16(acc[i][jp * 2 + 0], af[i], bfr[jp][0], bfr[jp][1]);
                    mma_f16(acc[i][jp * 2 + 1], af[i], bfr[jp][2], bfr[jp][3]);
                }
        }
        __syncthreads();
        if (c + 3 < NC) issue(c + 3, s);
        s = (s == 2) ? 0 : s + 1;
    }

#pragma unroll
    for (int i = 0; i < 4; i++) {
        long row = bm0 + wm * 64 + i * 16 + qr;
#pragma unroll
        for (int j = 0; j < 4; j++) {
            int col = bn0g * 8 + wn * 32 + j * 8 + 2 * qc;
            if (OUT_F16) {
                __half* C = (__half*)Cv;
                *(unsigned*)(C + row * ldc + col) = pack_f16(acc[i][j][0], acc[i][j][1]);
                *(unsigned*)(C + (row + 8) * ldc + col) = pack_f16(acc[i][j][2], acc[i][j][3]);
            } else {
                float* C = (float*)Cv;
                *(float2*)(C + row * ldc + col) = make_float2(acc[i][j][0], acc[i][j][1]);
                *(float2*)(C + (row + 8) * ldc + col) = make_float2(acc[i][j][2], acc[i][j][3]);
            }
        }
    }
}

// ======================= fp32 -> fp16 convert (granules of 8) ===============
__global__ __launch_bounds__(256) void cvtb_kernel(
    const float4* __restrict__ src, uint4* __restrict__ dst, long n)
{
    long i = (long)blockIdx.x * 256 + threadIdx.x;
    if (i >= n) return;
    float4 v0 = src[2 * i], v1 = src[2 * i + 1];
    dst[i] = make_uint4(pack_f16(v0.x, v0.y), pack_f16(v0.z, v0.w),
                        pack_f16(v1.x, v1.y), pack_f16(v1.z, v1.w));
}

// ======================= fp16 QK^T pass (ldmatrix + m16n8k16) ===============
// reads q,k granules directly from fp16 qkv (ld = 384 granules/row)
template <int MODE>
__global__ __launch_bounds__(256, 2) void qk_kernel(
    const uint4* __restrict__ qkv16, float* __restrict__ Z, float* __restrict__ colsum)
{
    __shared__ uint4 Qs[128 * 8];      // 16 KB
    __shared__ uint4 Ks[128 * 8];      // 16 KB
    __shared__ float s_red[512];

    const int tid = threadIdx.x, lane = tid & 31, wid = tid >> 5;
    const int wm = wid & 1, wn = wid >> 1, qr = lane >> 2, qc = lane & 3;
    const int bz = blockIdx.z;
    const int b = bz >> 4, h = bz & 15;
    const int bm0 = blockIdx.y * 128, bn0 = blockIdx.x * 128;

    const uint4* Qg = qkv16 + (long)b * SEQ * 384 + h * 8;
    const uint4* Kg = Qg + 128;        // k part starts at granule 128

    const int cg = tid & 7, rb = tid >> 3;
#pragma unroll
    for (int r = 0; r < 4; r++) {
        int row = rb + r * 32;
        uint4 vq = Qg[(long)(bm0 + row) * 384 + cg];
        uint4 vk = Kg[(long)(bn0 + row) * 384 + cg];
        int sw = row * 8 + (cg ^ (row & 7));
        Qs[sw] = vq;
        Ks[sw] = vk;
    }
    if (MODE == 2 && tid < 128)
        s_red[tid] = 1.0f / Z[(long)bz * SEQ + bm0 + tid];
    __syncthreads();

    float izreg[4][2];
    if (MODE == 2) {
#pragma unroll
        for (int i = 0; i < 4; i++)
#pragma unroll
            for (int h2 = 0; h2 < 2; h2++)
                izreg[i][h2] = s_red[wm * 64 + i * 16 + h2 * 8 + qr];
    }

    float acc[4][4][4];
#pragma unroll
    for (int i = 0; i < 4; i++)
#pragma unroll
        for (int j = 0; j < 4; j++)
#pragma unroll
            for (int f = 0; f < 4; f++) acc[i][j][f] = 0.f;

    const int grp = lane >> 3, lrow = lane & 7;
    const int a_roff = (grp & 1) * 8, a_kg = grp >> 1;
    const int b_roff = (grp >> 1) * 8, b_kg = grp & 1;

#pragma unroll
    for (int g = 0; g < 4; g++) {
        unsigned af[4][4], bfr[2][4];
#pragma unroll
        for (int i = 0; i < 4; i++) {
            int row = wm * 64 + i * 16 + lrow + a_roff;
            int gr = (2 * g + a_kg) ^ (row & 7);
            ldsm4(af[i], sptr(&Qs[row * 8 + gr]));
        }
#pragma unroll
        for (int jp = 0; jp < 2; jp++) {
            int row = wn * 32 + jp * 16 + lrow + b_roff;
            int gr = (2 * g + b_kg) ^ (row & 7);
            ldsm4(bfr[jp], sptr(&Ks[row * 8 + gr]));
        }
#pragma unroll
        for (int i = 0; i < 4; i++)
#pragma unroll
            for (int jp = 0; jp < 2; jp++) {
                mma_f16(acc[i][jp * 2 + 0], af[i], bfr[jp][0], bfr[jp][1]);
                mma_f16(acc[i][jp * 2 + 1], af[i], bfr[jp][2], bfr[jp][3]);
            }
    }

    if (MODE == 1) {
        float lz[4][2];
#pragma unroll
        for (int i = 0; i < 4; i++)
#pragma unroll
            for (int h2 = 0; h2 < 2; h2++) {
                float z = 0.f;
#pragma unroll
                for (int j = 0; j < 4; j++) {
                    z += ex2f(acc[i][j][2 * h2]     * C2EXP);
                    z += ex2f(acc[i][j][2 * h2 + 1] * C2EXP);
                }
                lz[i][h2] = z;
            }
#pragma unroll
        for (int d = 1; d <= 2; d <<= 1)
#pragma unroll
            for (int i = 0; i < 4; i++)
#pragma unroll
                for (int h2 = 0; h2 < 2; h2++)
                    lz[i][h2] += __shfl_xor_sync(0xffffffffu, lz[i][h2], d);
        __syncthreads();
        if (qc == 0)
#pragma unroll
            for (int i = 0; i < 4; i++)
#pragma unroll
                for (int h2 = 0; h2 < 2; h2++)
                    s_red[wn * 128 + wm * 64 + i * 16 + h2 * 8 + qr] = lz[i][h2];
        __syncthreads();
        if (tid < 128) {
            float z = s_red[tid] + s_red[128 + tid] + s_red[256 + tid] + s_red[384 + tid];
            atomicAdd(&Z[(long)bz * SEQ + bm0 + tid], z);
        }
    }

    if (MODE == 2) {
        float cs[4][2];
#pragma unroll
        for (int j = 0; j < 4; j++) { cs[j][0] = 0.f; cs[j][1] = 0.f; }
#pragma unroll
        for (int i = 0; i < 4; i++)
#pragma unroll
            for (int h2 = 0; h2 < 2; h2++) {
                float iz = izreg[i][h2];
#pragma unroll
                for (int j = 0; j < 4; j++) {
                    cs[j][0] += ex2f(acc[i][j][2 * h2]     * C2EXP) * iz;
                    cs[j][1] += ex2f(acc[i][j][2 * h2 + 1] * C2EXP) * iz;
                }
            }
#pragma unroll
        for (int d = 4; d <= 16; d <<= 1)
#pragma unroll
            for (int j = 0; j < 4; j++) {
                cs[j][0] += __shfl_xor_sync(0xffffffffu, cs[j][0], d);
                cs[j][1] += __shfl_xor_sync(0xffffffffu, cs[j][1], d);
            }
        if (qr == 0) {
#pragma unroll
            for (int j = 0; j < 4; j++) {
                int col = bn0 + wn * 32 + j * 8 + 2 * qc;
                atomicAdd(&colsum[(long)bz * SEQ + col],     cs[j][0]);
                atomicAdd(&colsum[(long)bz * SEQ + col + 1], cs[j][1]);
            }
        }
    }
}

// ======================= v * colsum -> fp16 vals ============================
__global__ __launch_bounds__(256) void scale_v16_kernel(
    const uint4* __restrict__ qkv16, const float* __restrict__ cs,
    uint4* __restrict__ vals16)
{
    long i = (long)blockIdx.x * 256 + threadIdx.x;   // BS*128 granules
    long bs = i >> 7;
    int fg = (int)(i & 127);
    int h = fg >> 3;
    int b = (int)(bs >> 11), s = (int)(bs & (SEQ - 1));
    float sc = cs[(((long)b << 4) + h) * SEQ + s];
    uint4 v = qkv16[bs * 384 + 256 + fg];
    uint4 o;
    unsigned* vp = (unsigned*)&v;
    unsigned* op = (unsigned*)&o;
#pragma unroll
    for (int j = 0; j < 4; j++) {
        float2 f = __half22float2(*(__half2*)&vp[j]);
        op[j] = pack_f16(f.x * sc, f.y * sc);
    }
    vals16[i] = o;
}

// ---------------- zero accumulators ----------------------------------------
__global__ void zero_kernel(float* __restrict__ z, float* __restrict__ cs)
{
    int i = blockIdx.x * 256 + threadIdx.x;
    if (i < NBH * SEQ) { z[i] = 0.f; cs[i] = 0.f; }
}

// ---------------- launcher --------------------------------------------------
#define GEMM_SMEM 98304

extern "C" void kernel_launch(void* const* d_in, const int* in_sizes, int n_in,
                              void* d_out, int out_size)
{
    const float* x     = (const float*)d_in[0];
    const float* w_qkv = (const float*)d_in[1];
    const float* w_o   = (const float*)d_in[2];
    float* out = (float*)d_out;

    float *p_z, *p_cs;
    uint4 *p_qkv16, *p_x16, *p_wq16, *p_wo16, *p_vals16;
    cudaGetSymbolAddress((void**)&p_z,      g_z);
    cudaGetSymbolAddress((void**)&p_cs,     g_colsum);
    cudaGetSymbolAddress((void**)&p_qkv16,  g_qkv16);
    cudaGetSymbolAddress((void**)&p_x16,    g_x16);
    cudaGetSymbolAddress((void**)&p_wq16,   g_wq16);
    cudaGetSymbolAddress((void**)&p_wo16,   g_wo16);
    cudaGetSymbolAddress((void**)&p_vals16, g_vals16);

    cudaFuncSetAttribute(gemm_f16<true>,  cudaFuncAttributeMaxDynamicSharedMemorySize, GEMM_SMEM);
    cudaFuncSetAttribute(gemm_f16<false>, cudaFuncAttributeMaxDynamicSharedMemorySize, GEMM_SMEM);

    dim3 blk(256);

    // 0. zero accumulators
    zero_kernel<<<(NBH * SEQ + 255) / 256, blk>>>(p_z, p_cs);

    // 0b. convert inputs to fp16
    cvtb_kernel<<<(int)(((long)BS * HID / 8 + 255) / 256), blk>>>(
        (const float4*)x, p_x16, (long)BS * HID / 8);
    cvtb_kernel<<<(int)(((long)HID * F3 / 8 + 255) / 256), blk>>>(
        (const float4*)w_qkv, p_wq16, (long)HID * F3 / 8);
    cvtb_kernel<<<(int)(((long)HID * HID / 8 + 255) / 256), blk>>>(
        (const float4*)w_o, p_wo16, (long)HID * HID / 8);

    // 1. qkv(fp16) = x16 @ wq16
    gemm_f16<true><<<dim3(F3 / 128, BS / 128), blk, GEMM_SMEM>>>(
        p_x16, p_wq16, p_qkv16, HID, HID / 8, F3 / 8, F3);

    // 2. pass 1: Z[q] = sum_k exp(q.k/8)
    qk_kernel<1><<<dim3(SEQ / 128, SEQ / 128, NBH), blk>>>(p_qkv16, p_z, nullptr);

    // 3. pass 2: colsum[k] = sum_q exp(q.k/8)/Z[q]
    qk_kernel<2><<<dim3(SEQ / 128, SEQ / 128, NBH), blk>>>(p_qkv16, p_z, p_cs);

    // 4. vals16 = fp16(v * colsum)
    scale_v16_kernel<<<(int)(((long)BS * HID / 8) / 256), blk>>>(p_qkv16, p_cs, p_vals16);

    // 5. out(fp32) = vals16 @ wo16
    gemm_f16<false><<<dim3(HID / 128, BS / 128), blk, GEMM_SMEM>>>(
        p_vals16, p_wo16, out, HID, HID / 8, HID / 8, HID);
}

// round 12
// speedup vs baseline: 1.5418x; 1.1225x over previous
#include <cuda_runtime.h>
#include <cuda_fp16.h>
#include <math.h>

#define BATCH 2
#define SEQ   2048
#define NH    16
#define HD    64
#define HID   1024
#define F3    3072
#define BS    (BATCH*SEQ)
#define NBH   (BATCH*NH)        // 32

// 0.125 * log2(e)
#define C2EXP 0.1803368801111204f

// ---------------- scratch (device globals) ---------------------------------
__device__ uint4 g_qkv16[(size_t)BS * F3 / 8];           // fp16 qkv, 25.2 MB
__device__ uint4 g_x16[(size_t)BS * HID / 8];            // fp16 x
__device__ uint4 g_wq16[(size_t)HID * F3 / 8];           // fp16 w_qkv
__device__ uint4 g_wo16[(size_t)HID * HID / 8];          // fp16 w_o
__device__ uint4 g_vals16[(size_t)BS * HID / 8];         // fp16 v*colsum
__device__ float g_z[NBH * SEQ];
__device__ float g_colsum[NBH * SEQ];

__device__ __forceinline__ float ex2f(float x) {
    float r; asm("ex2.approx.f32 %0, %1;" : "=f"(r) : "f"(x)); return r;
}
__device__ __forceinline__ unsigned sptr(const void* p) {
    return (unsigned)__cvta_generic_to_shared(p);
}
__device__ __forceinline__ void mma_f16(float* c, const unsigned* a, unsigned b0, unsigned b1) {
    asm volatile(
        "mma.sync.aligned.m16n8k16.row.col.f32.f16.f16.f32 "
        "{%0,%1,%2,%3}, {%4,%5,%6,%7}, {%8,%9}, {%0,%1,%2,%3};"
        : "+f"(c[0]), "+f"(c[1]), "+f"(c[2]), "+f"(c[3])
        : "r"(a[0]), "r"(a[1]), "r"(a[2]), "r"(a[3]), "r"(b0), "r"(b1));
}
__device__ __forceinline__ void ldsm4(unsigned* r, unsigned addr) {
    asm volatile("ldmatrix.sync.aligned.m8n8.x4.shared.b16 {%0,%1,%2,%3}, [%4];"
                 : "=r"(r[0]), "=r"(r[1]), "=r"(r[2]), "=r"(r[3]) : "r"(addr));
}
__device__ __forceinline__ void ldsm4t(unsigned* r, unsigned addr) {
    asm volatile("ldmatrix.sync.aligned.m8n8.x4.trans.shared.b16 {%0,%1,%2,%3}, [%4];"
                 : "=r"(r[0]), "=r"(r[1]), "=r"(r[2]), "=r"(r[3]) : "r"(addr));
}
__device__ __forceinline__ void cp16(unsigned dst, const void* src) {
    asm volatile("cp.async.cg.shared.global [%0], [%1], 16;" :: "r"(dst), "l"(src));
}
__device__ __forceinline__ unsigned pack_f16(float a, float b) {
    __half2 h = __floats2half2_rn(a, b);
    return *(unsigned*)&h;
}

// ======================= fp16 GEMM, 128x128 tile, cp.async 3-stage ==========
template <bool OUT_F16>
__global__ __launch_bounds__(256, 2) void gemm_f16(
    const uint4* __restrict__ A, const uint4* __restrict__ B, void* __restrict__ Cv,
    int K, int ldaG, int ldbG, int ldc)
{
    extern __shared__ uint4 smem[];
    uint4* sA = smem;           // [3][1024]
    uint4* sB = smem + 3072;    // [3][1024]

    const int tid = threadIdx.x, lane = tid & 31, wid = tid >> 5;
    const int wm = wid & 1, wn = wid >> 1, qr = lane >> 2, qc = lane & 3;
    const int grp = lane >> 3, lrow = lane & 7;
    const int bm0 = blockIdx.y * 128;
    const int bn0g = blockIdx.x * 16;
    const int NC = K / 64;

    const int cgA = tid & 7,  rowA0 = tid >> 3;
    const int cgB = tid & 15, rowB0 = tid >> 4;

    auto issue = [&](int c, int s) {
        const uint4* ag = A + (long)(bm0 + rowA0) * ldaG + c * 8 + cgA;
        uint4* ad = sA + s * 1024;
#pragma unroll
        for (int r = 0; r < 4; r++) {
            int row = rowA0 + r * 32;
            cp16(sptr(ad + row * 8 + (cgA ^ (row & 7))), ag + (long)r * 32 * ldaG);
        }
        const uint4* bg = B + (long)(c * 64 + rowB0) * ldbG + bn0g + cgB;
        uint4* bd = sB + s * 1024;
#pragma unroll
        for (int r = 0; r < 4; r++) {
            int row = rowB0 + r * 16;
            cp16(sptr(bd + row * 16 + (cgB ^ (row & 7))), bg + (long)r * 16 * ldbG);
        }
        asm volatile("cp.async.commit_group;");
    };

    issue(0, 0);
    if (NC > 1) issue(1, 1);
    if (NC > 2) issue(2, 2);

    float acc[4][4][4];
#pragma unroll
    for (int i = 0; i < 4; i++)
#pragma unroll
        for (int j = 0; j < 4; j++)
#pragma unroll
            for (int f = 0; f < 4; f++) acc[i][j][f] = 0.f;

    int s = 0;
#pragma unroll 1
    for (int c = 0; c < NC; c++) {
        asm volatile("cp.async.wait_group 2;");
        __syncthreads();
        const uint4* sAs = sA + s * 1024;
        const uint4* sBs = sB + s * 1024;

#pragma unroll
        for (int ks = 0; ks < 4; ks++) {
            unsigned af[4][4], bfr[2][4];
#pragma unroll
            for (int i = 0; i < 4; i++) {
                int row = wm * 64 + i * 16 + lrow + (grp & 1) * 8;
                int g = (2 * ks + (grp >> 1)) ^ (row & 7);
                ldsm4(af[i], sptr(sAs + row * 8 + g));
            }
#pragma unroll
            for (int jp = 0; jp < 2; jp++) {
                int brow = ks * 16 + (grp & 1) * 8 + lrow;
                int bg = (wn * 4 + jp * 2 + (grp >> 1)) ^ (brow & 7);
                ldsm4t(bfr[jp], sptr(sBs + brow * 16 + bg));
            }
#pragma unroll
            for (int i = 0; i < 4; i++)
#pragma unroll
                for (int jp = 0; jp < 2; jp++) {
                    mma_f16(acc[i][jp * 2 + 0], af[i], bfr[jp][0], bfr[jp][1]);
                    mma_f16(acc[i][jp * 2 + 1], af[i], bfr[jp][2], bfr[jp][3]);
                }
        }
        __syncthreads();
        if (c + 3 < NC) issue(c + 3, s);
        s = (s == 2) ? 0 : s + 1;
    }

#pragma unroll
    for (int i = 0; i < 4; i++) {
        long row = bm0 + wm * 64 + i * 16 + qr;
#pragma unroll
        for (int j = 0; j < 4; j++) {
            int col = bn0g * 8 + wn * 32 + j * 8 + 2 * qc;
            if (OUT_F16) {
                __half* C = (__half*)Cv;
                *(unsigned*)(C + row * ldc + col) = pack_f16(acc[i][j][0], acc[i][j][1]);
                *(unsigned*)(C + (row + 8) * ldc + col) = pack_f16(acc[i][j][2], acc[i][j][3]);
            } else {
                float* C = (float*)Cv;
                *(float2*)(C + row * ldc + col) = make_float2(acc[i][j][0], acc[i][j][1]);
                *(float2*)(C + (row + 8) * ldc + col) = make_float2(acc[i][j][2], acc[i][j][3]);
            }
        }
    }
}

// ======================= fp32 -> fp16 convert ===============================
__global__ __launch_bounds__(256) void cvtb_kernel(
    const float4* __restrict__ src, uint4* __restrict__ dst, long n)
{
    long i = (long)blockIdx.x * 256 + threadIdx.x;
    if (i >= n) return;
    float4 v0 = src[2 * i], v1 = src[2 * i + 1];
    dst[i] = make_uint4(pack_f16(v0.x, v0.y), pack_f16(v0.z, v0.w),
                        pack_f16(v1.x, v1.y), pack_f16(v1.z, v1.w));
}

// ======================= fp16 QK^T: 1 q-block x 4 key-blocks per CTA ========
// MODE 1: Z[q] += sum over 512 keys of exp(s)   (one atomic per row per CTA)
// MODE 2: colsum[k] += sum_q exp(s)/Z[q]        (per key-block atomics)
template <int MODE>
__global__ __launch_bounds__(256, 2) void qk_kernel(
    const uint4* __restrict__ qkv16, float* __restrict__ Z, float* __restrict__ colsum)
{
    __shared__ uint4 Qs[1024];         // 16 KB
    __shared__ uint4 Ks[2][1024];      // 32 KB double buffer
    __shared__ float s_red[512];

    const int tid = threadIdx.x, lane = tid & 31, wid = tid >> 5;
    const int wm = wid & 1, wn = wid >> 1, qr = lane >> 2, qc = lane & 3;
    const int bz = blockIdx.z;
    const int b = bz >> 4, h = bz & 15;
    const int bm0 = blockIdx.y * 128;
    const int bn_base = blockIdx.x * 512;

    const uint4* Qg = qkv16 + (long)b * SEQ * 384 + h * 8;
    const uint4* Kg = Qg + 128;

    const int cg = tid & 7, rb = tid >> 3;

    // Q tile (cp.async) + first K tile in one commit group
    {
        const uint4* qg = Qg + (long)(bm0 + rb) * 384 + cg;
#pragma unroll
        for (int r = 0; r < 4; r++) {
            int row = rb + r * 32;
            cp16(sptr(&Qs[row * 8 + (cg ^ (row & 7))]), qg + (long)r * 32 * 384);
        }
        const uint4* kg = Kg + (long)(bn_base + rb) * 384 + cg;
#pragma unroll
        for (int r = 0; r < 4; r++) {
            int row = rb + r * 32;
            cp16(sptr(&Ks[0][row * 8 + (cg ^ (row & 7))]), kg + (long)r * 32 * 384);
        }
        asm volatile("cp.async.commit_group;");
    }
    // second K tile
    {
        const uint4* kg = Kg + (long)(bn_base + 128 + rb) * 384 + cg;
#pragma unroll
        for (int r = 0; r < 4; r++) {
            int row = rb + r * 32;
            cp16(sptr(&Ks[1][row * 8 + (cg ^ (row & 7))]), kg + (long)r * 32 * 384);
        }
        asm volatile("cp.async.commit_group;");
    }

    if (MODE == 2 && tid < 128)
        s_red[tid] = 1.0f / Z[(long)bz * SEQ + bm0 + tid];

    const int grp = lane >> 3, lrow = lane & 7;
    const int a_roff = (grp & 1) * 8, a_kg = grp >> 1;
    const int b_roff = (grp >> 1) * 8, b_kg = grp & 1;

    float lz[4][2];                 // MODE1 row-exp accumulators
    float izreg[4][2];              // MODE2 1/Z registers
#pragma unroll
    for (int i = 0; i < 4; i++)
#pragma unroll
        for (int h2 = 0; h2 < 2; h2++) lz[i][h2] = 0.f;

#pragma unroll 1
    for (int nb = 0; nb < 4; nb++) {
        if (nb < 3) asm volatile("cp.async.wait_group 1;");
        else        asm volatile("cp.async.wait_group 0;");
        __syncthreads();

        if (nb == 0 && MODE == 2) {
#pragma unroll
            for (int i = 0; i < 4; i++)
#pragma unroll
                for (int h2 = 0; h2 < 2; h2++)
                    izreg[i][h2] = s_red[wm * 64 + i * 16 + h2 * 8 + qr];
        }

        float acc[4][4][4];
#pragma unroll
        for (int i = 0; i < 4; i++)
#pragma unroll
            for (int j = 0; j < 4; j++)
#pragma unroll
                for (int f = 0; f < 4; f++) acc[i][j][f] = 0.f;

        const uint4* Kb = Ks[nb & 1];
#pragma unroll
        for (int g = 0; g < 4; g++) {
            unsigned af[4][4], bfr[2][4];
#pragma unroll
            for (int i = 0; i < 4; i++) {
                int row = wm * 64 + i * 16 + lrow + a_roff;
                int gr = (2 * g + a_kg) ^ (row & 7);
                ldsm4(af[i], sptr(&Qs[row * 8 + gr]));
            }
#pragma unroll
            for (int jp = 0; jp < 2; jp++) {
                int row = wn * 32 + jp * 16 + lrow + b_roff;
                int gr = (2 * g + b_kg) ^ (row & 7);
                ldsm4(bfr[jp], sptr(&Kb[row * 8 + gr]));
            }
#pragma unroll
            for (int i = 0; i < 4; i++)
#pragma unroll
                for (int jp = 0; jp < 2; jp++) {
                    mma_f16(acc[i][jp * 2 + 0], af[i], bfr[jp][0], bfr[jp][1]);
                    mma_f16(acc[i][jp * 2 + 1], af[i], bfr[jp][2], bfr[jp][3]);
                }
        }
        __syncthreads();            // all warps done reading Ks[nb&1]

        // prefetch key-block nb+2 into the buffer just freed
        if (nb + 2 < 4) {
            const uint4* kg = Kg + (long)(bn_base + (nb + 2) * 128 + rb) * 384 + cg;
            uint4* kd = Ks[nb & 1];
#pragma unroll
            for (int r = 0; r < 4; r++) {
                int row = rb + r * 32;
                cp16(sptr(&kd[row * 8 + (cg ^ (row & 7))]), kg + (long)r * 32 * 384);
            }
            asm volatile("cp.async.commit_group;");
        }

        if (MODE == 1) {
#pragma unroll
            for (int i = 0; i < 4; i++)
#pragma unroll
                for (int h2 = 0; h2 < 2; h2++) {
#pragma unroll
                    for (int j = 0; j < 4; j++) {
                        lz[i][h2] += ex2f(acc[i][j][2 * h2]     * C2EXP);
                        lz[i][h2] += ex2f(acc[i][j][2 * h2 + 1] * C2EXP);
                    }
                }
        } else {
            float cs[4][2];
#pragma unroll
            for (int j = 0; j < 4; j++) { cs[j][0] = 0.f; cs[j][1] = 0.f; }
#pragma unroll
            for (int i = 0; i < 4; i++)
#pragma unroll
                for (int h2 = 0; h2 < 2; h2++) {
                    float iz = izreg[i][h2];
#pragma unroll
                    for (int j = 0; j < 4; j++) {
                        cs[j][0] += ex2f(acc[i][j][2 * h2]     * C2EXP) * iz;
                        cs[j][1] += ex2f(acc[i][j][2 * h2 + 1] * C2EXP) * iz;
                    }
                }
#pragma unroll
            for (int d = 4; d <= 16; d <<= 1)
#pragma unroll
                for (int j = 0; j < 4; j++) {
                    cs[j][0] += __shfl_xor_sync(0xffffffffu, cs[j][0], d);
                    cs[j][1] += __shfl_xor_sync(0xffffffffu, cs[j][1], d);
                }
            if (qr == 0) {
#pragma unroll
                for (int j = 0; j < 4; j++) {
                    int col = bn_base + nb * 128 + wn * 32 + j * 8 + 2 * qc;
                    atomicAdd(&colsum[(long)bz * SEQ + col],     cs[j][0]);
                    atomicAdd(&colsum[(long)bz * SEQ + col + 1], cs[j][1]);
                }
            }
        }
    }

    if (MODE == 1) {
#pragma unroll
        for (int d = 1; d <= 2; d <<= 1)
#pragma unroll
            for (int i = 0; i < 4; i++)
#pragma unroll
                for (int h2 = 0; h2 < 2; h2++)
                    lz[i][h2] += __shfl_xor_sync(0xffffffffu, lz[i][h2], d);
        __syncthreads();
        if (qc == 0)
#pragma unroll
            for (int i = 0; i < 4; i++)
#pragma unroll
                for (int h2 = 0; h2 < 2; h2++)
                    s_red[wn * 128 + wm * 64 + i * 16 + h2 * 8 + qr] = lz[i][h2];
        __syncthreads();
        if (tid < 128) {
            float z = s_red[tid] + s_red[128 + tid] + s_red[256 + tid] + s_red[384 + tid];
            atomicAdd(&Z[(long)bz * SEQ + bm0 + tid], z);
        }
    }
}

// ======================= v * colsum -> fp16 vals ============================
__global__ __launch_bounds__(256) void scale_v16_kernel(
    const uint4* __restrict__ qkv16, const float* __restrict__ cs,
    uint4* __restrict__ vals16)
{
    long i = (long)blockIdx.x * 256 + threadIdx.x;
    long bs = i >> 7;
    int fg = (int)(i & 127);
    int h = fg >> 3;
    int b = (int)(bs >> 11), s = (int)(bs & (SEQ - 1));
    float sc = cs[(((long)b << 4) + h) * SEQ + s];
    uint4 v = qkv16[bs * 384 + 256 + fg];
    uint4 o;
    unsigned* vp = (unsigned*)&v;
    unsigned* op = (unsigned*)&o;
#pragma unroll
    for (int j = 0; j < 4; j++) {
        float2 f = __half22float2(*(__half2*)&vp[j]);
        op[j] = pack_f16(f.x * sc, f.y * sc);
    }
    vals16[i] = o;
}

// ---------------- zero accumulators ----------------------------------------
__global__ void zero_kernel(float* __restrict__ z, float* __restrict__ cs)
{
    int i = blockIdx.x * 256 + threadIdx.x;
    if (i < NBH * SEQ) { z[i] = 0.f; cs[i] = 0.f; }
}

// ---------------- launcher --------------------------------------------------
#define GEMM_SMEM 98304

extern "C" void kernel_launch(void* const* d_in, const int* in_sizes, int n_in,
                              void* d_out, int out_size)
{
    const float* x     = (const float*)d_in[0];
    const float* w_qkv = (const float*)d_in[1];
    const float* w_o   = (const float*)d_in[2];
    float* out = (float*)d_out;

    float *p_z, *p_cs;
    uint4 *p_qkv16, *p_x16, *p_wq16, *p_wo16, *p_vals16;
    cudaGetSymbolAddress((void**)&p_z,      g_z);
    cudaGetSymbolAddress((void**)&p_cs,     g_colsum);
    cudaGetSymbolAddress((void**)&p_qkv16,  g_qkv16);
    cudaGetSymbolAddress((void**)&p_x16,    g_x16);
    cudaGetSymbolAddress((void**)&p_wq16,   g_wq16);
    cudaGetSymbolAddress((void**)&p_wo16,   g_wo16);
    cudaGetSymbolAddress((void**)&p_vals16, g_vals16);

    cudaFuncSetAttribute(gemm_f16<true>,  cudaFuncAttributeMaxDynamicSharedMemorySize, GEMM_SMEM);
    cudaFuncSetAttribute(gemm_f16<false>, cudaFuncAttributeMaxDynamicSharedMemorySize, GEMM_SMEM);

    dim3 blk(256);

    // 0. zero accumulators
    zero_kernel<<<(NBH * SEQ + 255) / 256, blk>>>(p_z, p_cs);

    // 0b. convert inputs to fp16
    cvtb_kernel<<<(int)(((long)BS * HID / 8 + 255) / 256), blk>>>(
        (const float4*)x, p_x16, (long)BS * HID / 8);
    cvtb_kernel<<<(int)(((long)HID * F3 / 8 + 255) / 256), blk>>>(
        (const float4*)w_qkv, p_wq16, (long)HID * F3 / 8);
    cvtb_kernel<<<(int)(((long)HID * HID / 8 + 255) / 256), blk>>>(
        (const float4*)w_o, p_wo16, (long)HID * HID / 8);

    // 1. qkv(fp16) = x16 @ wq16
    gemm_f16<true><<<dim3(F3 / 128, BS / 128), blk, GEMM_SMEM>>>(
        p_x16, p_wq16, p_qkv16, HID, HID / 8, F3 / 8, F3);

    // 2. pass 1: Z[q] = sum_k exp(q.k/8)
    qk_kernel<1><<<dim3(SEQ / 512, SEQ / 128, NBH), blk>>>(p_qkv16, p_z, nullptr);

    // 3. pass 2: colsum[k] = sum_q exp(q.k/8)/Z[q]
    qk_kernel<2><<<dim3(SEQ / 512, SEQ / 128, NBH), blk>>>(p_qkv16, p_z, p_cs);

    // 4. vals16 = fp16(v * colsum)
    scale_v16_kernel<<<(int)(((long)BS * HID / 8) / 256), blk>>>(p_qkv16, p_cs, p_vals16);

    // 5. out(fp32) = vals16 @ wo16
    gemm_f16<false><<<dim3(HID / 128, BS / 128), blk, GEMM_SMEM>>>(
        p_vals16, p_wo16, out, HID, HID / 8, HID / 8, HID);
}

// round 13
// speedup vs baseline: 2.3524x; 1.5258x over previous
#include <cuda_runtime.h>
#include <cuda_fp16.h>
#include <math.h>

#define BATCH 2
#define SEQ   2048
#define NH    16
#define HD    64
#define HID   1024
#define F3    3072
#define BS    (BATCH*SEQ)
#define NBH   (BATCH*NH)        // 32
#define QSTRIPS 2               // q-strips in qk2 (each 1024 rows = 8 tiles)

// 0.125 * log2(e)
#define C2EXP 0.1803368801111204f

// ---------------- scratch (device globals) ---------------------------------
__device__ uint4 g_qkv16[(size_t)BS * F3 / 8];           // fp16 qkv, 25.2 MB
__device__ uint4 g_x16[(size_t)BS * HID / 8];            // fp16 x
__device__ uint4 g_wq16[(size_t)HID * F3 / 8];           // fp16 w_qkv
__device__ uint4 g_wo16[(size_t)HID * HID / 8];          // fp16 w_o
__device__ uint4 g_vals16[(size_t)BS * HID / 8];         // fp16 v*colsum
__device__ float g_z[NBH * SEQ];
__device__ float g_colsum[NBH * SEQ];

__device__ __forceinline__ float ex2f(float x) {
    float r; asm("ex2.approx.f32 %0, %1;" : "=f"(r) : "f"(x)); return r;
}
__device__ __forceinline__ unsigned sptr(const void* p) {
    return (unsigned)__cvta_generic_to_shared(p);
}
__device__ __forceinline__ void mma_f16(float* c, const unsigned* a, unsigned b0, unsigned b1) {
    asm volatile(
        "mma.sync.aligned.m16n8k16.row.col.f32.f16.f16.f32 "
        "{%0,%1,%2,%3}, {%4,%5,%6,%7}, {%8,%9}, {%0,%1,%2,%3};"
        : "+f"(c[0]), "+f"(c[1]), "+f"(c[2]), "+f"(c[3])
        : "r"(a[0]), "r"(a[1]), "r"(a[2]), "r"(a[3]), "r"(b0), "r"(b1));
}
__device__ __forceinline__ void ldsm4(unsigned* r, unsigned addr) {
    asm volatile("ldmatrix.sync.aligned.m8n8.x4.shared.b16 {%0,%1,%2,%3}, [%4];"
                 : "=r"(r[0]), "=r"(r[1]), "=r"(r[2]), "=r"(r[3]) : "r"(addr));
}
__device__ __forceinline__ void ldsm4t(unsigned* r, unsigned addr) {
    asm volatile("ldmatrix.sync.aligned.m8n8.x4.trans.shared.b16 {%0,%1,%2,%3}, [%4];"
                 : "=r"(r[0]), "=r"(r[1]), "=r"(r[2]), "=r"(r[3]) : "r"(addr));
}
__device__ __forceinline__ void cp16(unsigned dst, const void* src) {
    asm volatile("cp.async.cg.shared.global [%0], [%1], 16;" :: "r"(dst), "l"(src));
}
__device__ __forceinline__ unsigned pack_f16(float a, float b) {
    __half2 h = __floats2half2_rn(a, b);
    return *(unsigned*)&h;
}

// ======================= fp16 GEMM, 128x128 tile, cp.async 3-stage ==========
template <bool OUT_F16>
__global__ __launch_bounds__(256, 2) void gemm_f16(
    const uint4* __restrict__ A, const uint4* __restrict__ B, void* __restrict__ Cv,
    int K, int ldaG, int ldbG, int ldc)
{
    extern __shared__ uint4 smem[];
    uint4* sA = smem;           // [3][1024]
    uint4* sB = smem + 3072;    // [3][1024]

    const int tid = threadIdx.x, lane = tid & 31, wid = tid >> 5;
    const int wm = wid & 1, wn = wid >> 1, qr = lane >> 2, qc = lane & 3;
    const int grp = lane >> 3, lrow = lane & 7;
    const int bm0 = blockIdx.y * 128;
    const int bn0g = blockIdx.x * 16;
    const int NC = K / 64;

    const int cgA = tid & 7,  rowA0 = tid >> 3;
    const int cgB = tid & 15, rowB0 = tid >> 4;

    auto issue = [&](int c, int s) {
        const uint4* ag = A + (long)(bm0 + rowA0) * ldaG + c * 8 + cgA;
        uint4* ad = sA + s * 1024;
#pragma unroll
        for (int r = 0; r < 4; r++) {
            int row = rowA0 + r * 32;
            cp16(sptr(ad + row * 8 + (cgA ^ (row & 7))), ag + (long)r * 32 * ldaG);
        }
        const uint4* bg = B + (long)(c * 64 + rowB0) * ldbG + bn0g + cgB;
        uint4* bd = sB + s * 1024;
#pragma unroll
        for (int r = 0; r < 4; r++) {
            int row = rowB0 + r * 16;
            cp16(sptr(bd + row * 16 + (cgB ^ (row & 7))), bg + (long)r * 16 * ldbG);
        }
        asm volatile("cp.async.commit_group;");
    };

    issue(0, 0);
    if (NC > 1) issue(1, 1);
    if (NC > 2) issue(2, 2);

    float acc[4][4][4];
#pragma unroll
    for (int i = 0; i < 4; i++)
#pragma unroll
        for (int j = 0; j < 4; j++)
#pragma unroll
            for (int f = 0; f < 4; f++) acc[i][j][f] = 0.f;

    int s = 0;
#pragma unroll 1
    for (int c = 0; c < NC; c++) {
        asm volatile("cp.async.wait_group 2;");
        __syncthreads();
        const uint4* sAs = sA + s * 1024;
        const uint4* sBs = sB + s * 1024;

#pragma unroll
        for (int ks = 0; ks < 4; ks++) {
            unsigned af[4][4], bfr[2][4];
#pragma unroll
            for (int i = 0; i < 4; i++) {
                int row = wm * 64 + i * 16 + lrow + (grp & 1) * 8;
                int g = (2 * ks + (grp >> 1)) ^ (row & 7);
                ldsm4(af[i], sptr(sAs + row * 8 + g));
            }
#pragma unroll
            for (int jp = 0; jp < 2; jp++) {
                int brow = ks * 16 + (grp & 1) * 8 + lrow;
                int bg = (wn * 4 + jp * 2 + (grp >> 1)) ^ (brow & 7);
                ldsm4t(bfr[jp], sptr(sBs + brow * 16 + bg));
            }
#pragma unroll
            for (int i = 0; i < 4; i++)
#pragma unroll
                for (int jp = 0; jp < 2; jp++) {
                    mma_f16(acc[i][jp * 2 + 0], af[i], bfr[jp][0], bfr[jp][1]);
                    mma_f16(acc[i][jp * 2 + 1], af[i], bfr[jp][2], bfr[jp][3]);
                }
        }
        __syncthreads();
        if (c + 3 < NC) issue(c + 3, s);
        s = (s == 2) ? 0 : s + 1;
    }

#pragma unroll
    for (int i = 0; i < 4; i++) {
        long row = bm0 + wm * 64 + i * 16 + qr;
#pragma unroll
        for (int j = 0; j < 4; j++) {
            int col = bn0g * 8 + wn * 32 + j * 8 + 2 * qc;
            if (OUT_F16) {
                __half* C = (__half*)Cv;
                *(unsigned*)(C + row * ldc + col) = pack_f16(acc[i][j][0], acc[i][j][1]);
                *(unsigned*)(C + (row + 8) * ldc + col) = pack_f16(acc[i][j][2], acc[i][j][3]);
            } else {
                float* C = (float*)Cv;
                *(float2*)(C + row * ldc + col) = make_float2(acc[i][j][0], acc[i][j][1]);
                *(float2*)(C + (row + 8) * ldc + col) = make_float2(acc[i][j][2], acc[i][j][3]);
            }
        }
    }
}

// ======================= fused fp32 -> fp16 convert (x, w_qkv, w_o) =========
#define N_X  ((long)BS * HID / 8)        // 524288
#define N_WQ ((long)HID * F3 / 8)        // 393216
#define N_WO ((long)HID * HID / 8)       // 131072

__global__ __launch_bounds__(256) void cvt_all_kernel(
    const float4* __restrict__ x, const float4* __restrict__ wq,
    const float4* __restrict__ wo,
    uint4* __restrict__ x16, uint4* __restrict__ wq16, uint4* __restrict__ wo16)
{
    long i = (long)blockIdx.x * 256 + threadIdx.x;
    const float4* src;
    uint4* dst;
    long j;
    if (i < N_X)              { src = x;  dst = x16;  j = i; }
    else if (i < N_X + N_WQ)  { src = wq; dst = wq16; j = i - N_X; }
    else                      { src = wo; dst = wo16; j = i - N_X - N_WQ; }
    float4 v0 = src[2 * j], v1 = src[2 * j + 1];
    dst[j] = make_uint4(pack_f16(v0.x, v0.y), pack_f16(v0.z, v0.w),
                        pack_f16(v1.x, v1.y), pack_f16(v1.z, v1.w));
}

// ======================= qk pass 1: Z[q] += sum over 512 keys of exp(s) =====
// 1 q-block x 4 key-blocks per CTA (round-12 validated)
__global__ __launch_bounds__(256, 2) void qk1_kernel(
    const uint4* __restrict__ qkv16, float* __restrict__ Z)
{
    __shared__ uint4 Qs[1024];         // 16 KB
    __shared__ uint4 Ks[2][1024];      // 32 KB double buffer
    __shared__ float s_red[512];

    const int tid = threadIdx.x, lane = tid & 31, wid = tid >> 5;
    const int wm = wid & 1, wn = wid >> 1, qr = lane >> 2, qc = lane & 3;
    const int bz = blockIdx.z;
    const int b = bz >> 4, h = bz & 15;
    const int bm0 = blockIdx.y * 128;
    const int bn_base = blockIdx.x * 512;

    const uint4* Qg = qkv16 + (long)b * SEQ * 384 + h * 8;
    const uint4* Kg = Qg + 128;

    const int cg = tid & 7, rb = tid >> 3;

    {
        const uint4* qg = Qg + (long)(bm0 + rb) * 384 + cg;
#pragma unroll
        for (int r = 0; r < 4; r++) {
            int row = rb + r * 32;
            cp16(sptr(&Qs[row * 8 + (cg ^ (row & 7))]), qg + (long)r * 32 * 384);
        }
        const uint4* kg = Kg + (long)(bn_base + rb) * 384 + cg;
#pragma unroll
        for (int r = 0; r < 4; r++) {
            int row = rb + r * 32;
            cp16(sptr(&Ks[0][row * 8 + (cg ^ (row & 7))]), kg + (long)r * 32 * 384);
        }
        asm volatile("cp.async.commit_group;");
    }
    {
        const uint4* kg = Kg + (long)(bn_base + 128 + rb) * 384 + cg;
#pragma unroll
        for (int r = 0; r < 4; r++) {
            int row = rb + r * 32;
            cp16(sptr(&Ks[1][row * 8 + (cg ^ (row & 7))]), kg + (long)r * 32 * 384);
        }
        asm volatile("cp.async.commit_group;");
    }

    const int grp = lane >> 3, lrow = lane & 7;
    const int a_roff = (grp & 1) * 8, a_kg = grp >> 1;
    const int b_roff = (grp >> 1) * 8, b_kg = grp & 1;

    float lz[4][2];
#pragma unroll
    for (int i = 0; i < 4; i++)
#pragma unroll
        for (int h2 = 0; h2 < 2; h2++) lz[i][h2] = 0.f;

#pragma unroll 1
    for (int nb = 0; nb < 4; nb++) {
        if (nb < 3) asm volatile("cp.async.wait_group 1;");
        else        asm volatile("cp.async.wait_group 0;");
        __syncthreads();

        float acc[4][4][4];
#pragma unroll
        for (int i = 0; i < 4; i++)
#pragma unroll
            for (int j = 0; j < 4; j++)
#pragma unroll
                for (int f = 0; f < 4; f++) acc[i][j][f] = 0.f;

        const uint4* Kb = Ks[nb & 1];
#pragma unroll
        for (int g = 0; g < 4; g++) {
            unsigned af[4][4], bfr[2][4];
#pragma unroll
            for (int i = 0; i < 4; i++) {
                int row = wm * 64 + i * 16 + lrow + a_roff;
                int gr = (2 * g + a_kg) ^ (row & 7);
                ldsm4(af[i], sptr(&Qs[row * 8 + gr]));
            }
#pragma unroll
            for (int jp = 0; jp < 2; jp++) {
                int row = wn * 32 + jp * 16 + lrow + b_roff;
                int gr = (2 * g + b_kg) ^ (row & 7);
                ldsm4(bfr[jp], sptr(&Kb[row * 8 + gr]));
            }
#pragma unroll
            for (int i = 0; i < 4; i++)
#pragma unroll
                for (int jp = 0; jp < 2; jp++) {
                    mma_f16(acc[i][jp * 2 + 0], af[i], bfr[jp][0], bfr[jp][1]);
                    mma_f16(acc[i][jp * 2 + 1], af[i], bfr[jp][2], bfr[jp][3]);
                }
        }
        __syncthreads();

        if (nb + 2 < 4) {
            const uint4* kg = Kg + (long)(bn_base + (nb + 2) * 128 + rb) * 384 + cg;
            uint4* kd = Ks[nb & 1];
#pragma unroll
            for (int r = 0; r < 4; r++) {
                int row = rb + r * 32;
                cp16(sptr(&kd[row * 8 + (cg ^ (row & 7))]), kg + (long)r * 32 * 384);
            }
            asm volatile("cp.async.commit_group;");
        }

#pragma unroll
        for (int i = 0; i < 4; i++)
#pragma unroll
            for (int h2 = 0; h2 < 2; h2++) {
#pragma unroll
                for (int j = 0; j < 4; j++) {
                    lz[i][h2] += ex2f(acc[i][j][2 * h2]     * C2EXP);
                    lz[i][h2] += ex2f(acc[i][j][2 * h2 + 1] * C2EXP);
                }
            }
    }

#pragma unroll
    for (int d = 1; d <= 2; d <<= 1)
#pragma unroll
        for (int i = 0; i < 4; i++)
#pragma unroll
            for (int h2 = 0; h2 < 2; h2++)
                lz[i][h2] += __shfl_xor_sync(0xffffffffu, lz[i][h2], d);
    __syncthreads();
    if (qc == 0)
#pragma unroll
        for (int i = 0; i < 4; i++)
#pragma unroll
            for (int h2 = 0; h2 < 2; h2++)
                s_red[wn * 128 + wm * 64 + i * 16 + h2 * 8 + qr] = lz[i][h2];
    __syncthreads();
    if (tid < 128) {
        float z = s_red[tid] + s_red[128 + tid] + s_red[256 + tid] + s_red[384 + tid];
        atomicAdd(&Z[(long)bz * SEQ + bm0 + tid], z);
    }
}

// ======================= qk pass 2 (transposed): K resident, Q streamed =====
// CTA: one key-block (128 cols) x one q-strip (1024 rows = 8 tiles).
// colsum accumulated in registers over the strip; one atomic set at the end.
__global__ __launch_bounds__(256, 2) void qk2_kernel(
    const uint4* __restrict__ qkv16, const float* __restrict__ Z,
    float* __restrict__ colsum)
{
    extern __shared__ uint4 dsm[];
    uint4* Ks   = dsm;               // 1024 granules (16 KB), resident
    uint4* Qs   = dsm + 1024;        // 2 x 1024 granules (32 KB) double buffer
    float* s_iz = (float*)(dsm + 3072);   // 1024 floats (strip 1/Z)
    float* s_red = s_iz + 1024;           // 256 floats

    const int tid = threadIdx.x, lane = tid & 31, wid = tid >> 5;
    const int wm = wid & 1, wn = wid >> 1, qr = lane >> 2, qc = lane & 3;
    const int bz = blockIdx.z;
    const int b = bz >> 4, h = bz & 15;
    const int kb0 = blockIdx.x * 128;
    const int q0  = blockIdx.y * (SEQ / QSTRIPS);     // 1024-row strip

    const uint4* Qg = qkv16 + (long)b * SEQ * 384 + h * 8;
    const uint4* Kg = Qg + 128;

    const int cg = tid & 7, rb = tid >> 3;

    // K tile + Q tile 0 (group A)
    {
        const uint4* kg = Kg + (long)(kb0 + rb) * 384 + cg;
#pragma unroll
        for (int r = 0; r < 4; r++) {
            int row = rb + r * 32;
            cp16(sptr(&Ks[row * 8 + (cg ^ (row & 7))]), kg + (long)r * 32 * 384);
        }
        const uint4* qg = Qg + (long)(q0 + rb) * 384 + cg;
#pragma unroll
        for (int r = 0; r < 4; r++) {
            int row = rb + r * 32;
            cp16(sptr(&Qs[row * 8 + (cg ^ (row & 7))]), qg + (long)r * 32 * 384);
        }
        asm volatile("cp.async.commit_group;");
    }
    // Q tile 1 (group B)
    {
        const uint4* qg = Qg + (long)(q0 + 128 + rb) * 384 + cg;
#pragma unroll
        for (int r = 0; r < 4; r++) {
            int row = rb + r * 32;
            cp16(sptr(&Qs[1024 + row * 8 + (cg ^ (row & 7))]), qg + (long)r * 32 * 384);
        }
        asm volatile("cp.async.commit_group;");
    }

    // stage 1/Z for the whole strip (4 values per thread)
#pragma unroll
    for (int r = 0; r < 4; r++) {
        int idx = tid + r * 256;
        s_iz[idx] = 1.0f / Z[(long)bz * SEQ + q0 + idx];
    }

    const int grp = lane >> 3, lrow = lane & 7;
    const int a_roff = (grp & 1) * 8, a_kg = grp >> 1;
    const int b_roff = (grp >> 1) * 8, b_kg = grp & 1;

    float cs[4][2];
#pragma unroll
    for (int j = 0; j < 4; j++) { cs[j][0] = 0.f; cs[j][1] = 0.f; }

#pragma unroll 1
    for (int qt = 0; qt < 8; qt++) {
        if (qt < 7) asm volatile("cp.async.wait_group 1;");
        else        asm volatile("cp.async.wait_group 0;");
        __syncthreads();

        float izreg[4][2];
#pragma unroll
        for (int i = 0; i < 4; i++)
#pragma unroll
            for (int h2 = 0; h2 < 2; h2++)
                izreg[i][h2] = s_iz[qt * 128 + wm * 64 + i * 16 + h2 * 8 + qr];

        float acc[4][4][4];
#pragma unroll
        for (int i = 0; i < 4; i++)
#pragma unroll
            for (int j = 0; j < 4; j++)
#pragma unroll
                for (int f = 0; f < 4; f++) acc[i][j][f] = 0.f;

        const uint4* Qb = Qs + (qt & 1) * 1024;
#pragma unroll
        for (int g = 0; g < 4; g++) {
            unsigned af[4][4], bfr[2][4];
#pragma unroll
            for (int i = 0; i < 4; i++) {
                int row = wm * 64 + i * 16 + lrow + a_roff;
                int gr = (2 * g + a_kg) ^ (row & 7);
                ldsm4(af[i], sptr(&Qb[row * 8 + gr]));
            }
#pragma unroll
            for (int jp = 0; jp < 2; jp++) {
                int row = wn * 32 + jp * 16 + lrow + b_roff;
                int gr = (2 * g + b_kg) ^ (row & 7);
                ldsm4(bfr[jp], sptr(&Ks[row * 8 + gr]));
            }
#pragma unroll
            for (int i = 0; i < 4; i++)
#pragma unroll
                for (int jp = 0; jp < 2; jp++) {
                    mma_f16(acc[i][jp * 2 + 0], af[i], bfr[jp][0], bfr[jp][1]);
                    mma_f16(acc[i][jp * 2 + 1], af[i], bfr[jp][2], bfr[jp][3]);
                }
        }
        __syncthreads();

        // prefetch Q tile qt+2 into freed buffer
        if (qt + 2 < 8) {
            const uint4* qg = Qg + (long)(q0 + (qt + 2) * 128 + rb) * 384 + cg;
            uint4* qd = Qs + (qt & 1) * 1024;
#pragma unroll
            for (int r = 0; r < 4; r++) {
                int row = rb + r * 32;
                cp16(sptr(&qd[row * 8 + (cg ^ (row & 7))]), qg + (long)r * 32 * 384);
            }
            asm volatile("cp.async.commit_group;");
        }

#pragma unroll
        for (int i = 0; i < 4; i++)
#pragma unroll
            for (int h2 = 0; h2 < 2; h2++) {
                float iz = izreg[i][h2];
#pragma unroll
                for (int j = 0; j < 4; j++) {
                    cs[j][0] += ex2f(acc[i][j][2 * h2]     * C2EXP) * iz;
                    cs[j][1] += ex2f(acc[i][j][2 * h2 + 1] * C2EXP) * iz;
                }
            }
    }

    // reduce over qr lanes, combine the two wm warps, one atomic per column
#pragma unroll
    for (int d = 4; d <= 16; d <<= 1)
#pragma unroll
        for (int j = 0; j < 4; j++) {
            cs[j][0] += __shfl_xor_sync(0xffffffffu, cs[j][0], d);
            cs[j][1] += __shfl_xor_sync(0xffffffffu, cs[j][1], d);
        }
    if (qr == 0) {
#pragma unroll
        for (int j = 0; j < 4; j++) {
            s_red[wm * 128 + wn * 32 + j * 8 + 2 * qc]     = cs[j][0];
            s_red[wm * 128 + wn * 32 + j * 8 + 2 * qc + 1] = cs[j][1];
        }
    }
    __syncthreads();
    if (tid < 128) {
        float v = s_red[tid] + s_red[128 + tid];
        atomicAdd(&colsum[(long)bz * SEQ + kb0 + tid], v);
    }
}

// ======================= v * colsum -> fp16 vals ============================
__global__ __launch_bounds__(256) void scale_v16_kernel(
    const uint4* __restrict__ qkv16, const float* __restrict__ cs,
    uint4* __restrict__ vals16)
{
    long i = (long)blockIdx.x * 256 + threadIdx.x;
    long bs = i >> 7;
    int fg = (int)(i & 127);
    int h = fg >> 3;
    int b = (int)(bs >> 11), s = (int)(bs & (SEQ - 1));
    float sc = cs[(((long)b << 4) + h) * SEQ + s];
    uint4 v = qkv16[bs * 384 + 256 + fg];
    uint4 o;
    unsigned* vp = (unsigned*)&v;
    unsigned* op = (unsigned*)&o;
#pragma unroll
    for (int j = 0; j < 4; j++) {
        float2 f = __half22float2(*(__half2*)&vp[j]);
        op[j] = pack_f16(f.x * sc, f.y * sc);
    }
    vals16[i] = o;
}

// ---------------- zero accumulators ----------------------------------------
__global__ void zero_kernel(float* __restrict__ z, float* __restrict__ cs)
{
    int i = blockIdx.x * 256 + threadIdx.x;
    if (i < NBH * SEQ) { z[i] = 0.f; cs[i] = 0.f; }
}

// ---------------- launcher --------------------------------------------------
#define GEMM_SMEM 98304
#define QK2_SMEM  (49152 + 4096 + 1024 + 128)   // Ks+Qs + s_iz + s_red + pad

extern "C" void kernel_launch(void* const* d_in, const int* in_sizes, int n_in,
                              void* d_out, int out_size)
{
    const float* x     = (const float*)d_in[0];
    const float* w_qkv = (const float*)d_in[1];
    const float* w_o   = (const float*)d_in[2];
    float* out = (float*)d_out;

    float *p_z, *p_cs;
    uint4 *p_qkv16, *p_x16, *p_wq16, *p_wo16, *p_vals16;
    cudaGetSymbolAddress((void**)&p_z,      g_z);
    cudaGetSymbolAddress((void**)&p_cs,     g_colsum);
    cudaGetSymbolAddress((void**)&p_qkv16,  g_qkv16);
    cudaGetSymbolAddress((void**)&p_x16,    g_x16);
    cudaGetSymbolAddress((void**)&p_wq16,   g_wq16);
    cudaGetSymbolAddress((void**)&p_wo16,   g_wo16);
    cudaGetSymbolAddress((void**)&p_vals16, g_vals16);

    cudaFuncSetAttribute(gemm_f16<true>,  cudaFuncAttributeMaxDynamicSharedMemorySize, GEMM_SMEM);
    cudaFuncSetAttribute(gemm_f16<false>, cudaFuncAttributeMaxDynamicSharedMemorySize, GEMM_SMEM);
    cudaFuncSetAttribute(qk2_kernel, cudaFuncAttributeMaxDynamicSharedMemorySize, QK2_SMEM);

    dim3 blk(256);

    // 0. zero accumulators
    zero_kernel<<<(NBH * SEQ + 255) / 256, blk>>>(p_z, p_cs);

    // 0b. convert all inputs to fp16 (one kernel)
    cvt_all_kernel<<<(int)((N_X + N_WQ + N_WO) / 256), blk>>>(
        (const float4*)x, (const float4*)w_qkv, (const float4*)w_o,
        p_x16, p_wq16, p_wo16);

    // 1. qkv(fp16) = x16 @ wq16
    gemm_f16<true><<<dim3(F3 / 128, BS / 128), blk, GEMM_SMEM>>>(
        p_x16, p_wq16, p_qkv16, HID, HID / 8, F3 / 8, F3);

    // 2. pass 1: Z[q] = sum_k exp(q.k/8)
    qk1_kernel<<<dim3(SEQ / 512, SEQ / 128, NBH), blk>>>(p_qkv16, p_z);

    // 3. pass 2 (transposed): colsum[k] = sum_q exp(q.k/8)/Z[q]
    qk2_kernel<<<dim3(SEQ / 128, QSTRIPS, NBH), blk, QK2_SMEM>>>(p_qkv16, p_z, p_cs);

    // 4. vals16 = fp16(v * colsum)
    scale_v16_kernel<<<(int)(((long)BS * HID / 8) / 256), blk>>>(p_qkv16, p_cs, p_vals16);

    // 5. out(fp32) = vals16 @ wo16
    gemm_f16<false><<<dim3(HID / 128, BS / 128), blk, GEMM_SMEM>>>(
        p_vals16, p_wo16, out, HID, HID / 8, HID / 8, HID);
}